// round 5
// baseline (speedup 1.0000x reference)
#include <cuda_runtime.h>

// Flat dot-product reduction:
//   out = (1/N) * sum_i probs[i] * centroids[i]   over all N*K = 101,000,000 elems
// Pure HBM-streaming problem: 808 MB read once. Target ~7 TB/s -> ~115 us.

static const long long TOTAL_ELEMS = 101000000LL;   // N=1e6 * K=101
static const long long N_ROWS      = 1000000LL;

__device__ double g_acc;

__global__ void zero_acc_kernel() {
    g_acc = 0.0;
}

__global__ void dot_kernel(const float4* __restrict__ p,
                           const float4* __restrict__ c,
                           long long n4) {
    // 4 independent accumulators for ILP; float4 loads -> LDG.128
    float a0 = 0.f, a1 = 0.f, a2 = 0.f, a3 = 0.f;
    long long stride = (long long)gridDim.x * blockDim.x;
    long long i = (long long)blockIdx.x * blockDim.x + threadIdx.x;

    // 2-deep manual unroll: two float4 pairs in flight per iteration
    // (batched front LDGs -> higher MLP to hide DRAM latency)
    for (; i + stride < n4; i += 2 * stride) {
        float4 pv0 = p[i];
        float4 cv0 = c[i];
        float4 pv1 = p[i + stride];
        float4 cv1 = c[i + stride];
        a0 = fmaf(pv0.x, cv0.x, a0);
        a1 = fmaf(pv0.y, cv0.y, a1);
        a2 = fmaf(pv0.z, cv0.z, a2);
        a3 = fmaf(pv0.w, cv0.w, a3);
        a0 = fmaf(pv1.x, cv1.x, a0);
        a1 = fmaf(pv1.y, cv1.y, a1);
        a2 = fmaf(pv1.z, cv1.z, a2);
        a3 = fmaf(pv1.w, cv1.w, a3);
    }
    if (i < n4) {
        float4 pv = p[i];
        float4 cv = c[i];
        a0 = fmaf(pv.x, cv.x, a0);
        a1 = fmaf(pv.y, cv.y, a1);
        a2 = fmaf(pv.z, cv.z, a2);
        a3 = fmaf(pv.w, cv.w, a3);
    }

    float s = (a0 + a1) + (a2 + a3);

    // warp reduce
    #pragma unroll
    for (int o = 16; o > 0; o >>= 1)
        s += __shfl_xor_sync(0xffffffffu, s, o);

    // block reduce across warps
    __shared__ float warp_sums[8];  // 256 threads = 8 warps
    int lane = threadIdx.x & 31;
    int wid  = threadIdx.x >> 5;
    if (lane == 0) warp_sums[wid] = s;
    __syncthreads();
    if (wid == 0) {
        float v = (lane < (blockDim.x >> 5)) ? warp_sums[lane] : 0.f;
        #pragma unroll
        for (int o = 4; o > 0; o >>= 1)
            v += __shfl_xor_sync(0xffffffffu, v, o);
        if (lane == 0)
            atomicAdd(&g_acc, (double)v);
    }
}

__global__ void finalize_kernel(float* __restrict__ out, double inv_n) {
    out[0] = (float)(g_acc * inv_n);
}

extern "C" void kernel_launch(void* const* d_in, const int* in_sizes, int n_in,
                              void* d_out, int out_size) {
    const float4* probs     = (const float4*)d_in[0];
    const float4* centroids = (const float4*)d_in[1];
    float* out = (float*)d_out;

    long long total = (long long)in_sizes[0];       // 101,000,000 (divisible by 4)
    long long n4 = total >> 2;                      // 25,250,000 float4s
    long long n_rows = N_ROWS;
    // Derive row count from sizes if possible (K=101 fixed)
    if (total % 101LL == 0) n_rows = total / 101LL;

    zero_acc_kernel<<<1, 1>>>();

    const int threads = 256;
    const int blocks  = 2048;   // ~14 CTAs/SM worth of grid-stride work
    dot_kernel<<<blocks, threads>>>(probs, centroids, n4);

    finalize_kernel<<<1, 1>>>(out, 1.0 / (double)n_rows);
}

// round 6
// speedup vs baseline: 1.0003x; 1.0003x over previous
#include <cuda_runtime.h>

// out = (1/N) * sum_i probs[i] * centroids[i], N*K = 101,000,000 fp32 elems.
// Pure HBM stream: 808 MB read once. Single fused kernel (no zero/finalize
// launches): last-block-done pattern with a self-resetting atomicInc counter,
// so the kernel is deterministic across CUDA-graph replays.

__device__ double g_acc;            // zero at module load; reset by last block each run
__device__ unsigned int g_count;    // self-wraps to 0 via atomicInc(val = grid-1)

__global__ void dot_kernel(const float4* __restrict__ p,
                           const float4* __restrict__ c,
                           long long n4,
                           float* __restrict__ out,
                           double inv_n) {
    // 4 independent fp32 accumulators for ILP; float4 loads -> LDG.128
    float a0 = 0.f, a1 = 0.f, a2 = 0.f, a3 = 0.f;
    long long stride = (long long)gridDim.x * blockDim.x;
    long long i = (long long)blockIdx.x * blockDim.x + threadIdx.x;

    // 2-deep unroll: 4 x LDG.128 batched up front per iter (MLP to hide DRAM lat)
    for (; i + stride < n4; i += 2 * stride) {
        float4 pv0 = p[i];
        float4 cv0 = c[i];
        float4 pv1 = p[i + stride];
        float4 cv1 = c[i + stride];
        a0 = fmaf(pv0.x, cv0.x, a0);
        a1 = fmaf(pv0.y, cv0.y, a1);
        a2 = fmaf(pv0.z, cv0.z, a2);
        a3 = fmaf(pv0.w, cv0.w, a3);
        a0 = fmaf(pv1.x, cv1.x, a0);
        a1 = fmaf(pv1.y, cv1.y, a1);
        a2 = fmaf(pv1.z, cv1.z, a2);
        a3 = fmaf(pv1.w, cv1.w, a3);
    }
    if (i < n4) {
        float4 pv = p[i];
        float4 cv = c[i];
        a0 = fmaf(pv.x, cv.x, a0);
        a1 = fmaf(pv.y, cv.y, a1);
        a2 = fmaf(pv.z, cv.z, a2);
        a3 = fmaf(pv.w, cv.w, a3);
    }

    float s = (a0 + a1) + (a2 + a3);

    // warp reduce
    #pragma unroll
    for (int o = 16; o > 0; o >>= 1)
        s += __shfl_xor_sync(0xffffffffu, s, o);

    // block reduce across warps
    __shared__ float warp_sums[8];      // 256 threads = 8 warps
    int lane = threadIdx.x & 31;
    int wid  = threadIdx.x >> 5;
    if (lane == 0) warp_sums[wid] = s;
    __syncthreads();

    if (wid == 0) {
        float v = (lane < (blockDim.x >> 5)) ? warp_sums[lane] : 0.f;
        #pragma unroll
        for (int o = 4; o > 0; o >>= 1)
            v += __shfl_xor_sync(0xffffffffu, v, o);

        if (lane == 0) {
            atomicAdd(&g_acc, (double)v);
            __threadfence();
            // atomicInc with val = gridDim-1: returns old, wraps to 0 on the
            // last block -> counter is self-resetting across graph replays.
            unsigned int t = atomicInc(&g_count, gridDim.x - 1);
            if (t == gridDim.x - 1) {
                // read through the L2 atomic path (coherent with the adds)
                double total = atomicAdd(&g_acc, 0.0);
                out[0] = (float)(total * inv_n);
                g_acc = 0.0;   // reset for next replay
            }
        }
    }
}

extern "C" void kernel_launch(void* const* d_in, const int* in_sizes, int n_in,
                              void* d_out, int out_size) {
    const float4* probs     = (const float4*)d_in[0];
    const float4* centroids = (const float4*)d_in[1];
    float* out = (float*)d_out;

    long long total = (long long)in_sizes[0];     // 101,000,000 (divisible by 4)
    long long n4 = total >> 2;
    long long n_rows = (total % 101LL == 0) ? (total / 101LL) : 1000000LL;

    const int threads = 256;
    const int blocks  = 2048;
    dot_kernel<<<blocks, threads>>>(probs, centroids, n4, out,
                                    1.0 / (double)n_rows);
}

// round 9
// speedup vs baseline: 1.0041x; 1.0038x over previous
#include <cuda_runtime.h>

// out = (1/N) * sum_i probs[i] * centroids[i], N*K = 101,000,000 fp32 elems.
// Pure HBM stream: 808 MB read once, currently 6.95 TB/s (86.9% of spec).
// This round: single persistent wave (740 = 148 SMs x 5 CTAs, matching the
// reg-limited residency) to kill wave-quantization tails, plus evict-first
// streaming loads (__ldcs) since there is zero reuse.

__device__ double g_acc;            // reset by last block each run (graph-replay safe)
__device__ unsigned int g_count;    // self-wraps via atomicInc(val = grid-1)

__global__ void __launch_bounds__(256)
dot_kernel(const float4* __restrict__ p,
           const float4* __restrict__ c,
           long long n4,
           float* __restrict__ out,
           double inv_n) {
    float a0 = 0.f, a1 = 0.f, a2 = 0.f, a3 = 0.f;
    long long stride = (long long)gridDim.x * blockDim.x;
    long long i = (long long)blockIdx.x * blockDim.x + threadIdx.x;

    // 2-deep unroll: 4 x LDG.128 (evict-first) batched up front per iter.
    for (; i + stride < n4; i += 2 * stride) {
        float4 pv0 = __ldcs(p + i);
        float4 cv0 = __ldcs(c + i);
        float4 pv1 = __ldcs(p + i + stride);
        float4 cv1 = __ldcs(c + i + stride);
        a0 = fmaf(pv0.x, cv0.x, a0);
        a1 = fmaf(pv0.y, cv0.y, a1);
        a2 = fmaf(pv0.z, cv0.z, a2);
        a3 = fmaf(pv0.w, cv0.w, a3);
        a0 = fmaf(pv1.x, cv1.x, a0);
        a1 = fmaf(pv1.y, cv1.y, a1);
        a2 = fmaf(pv1.z, cv1.z, a2);
        a3 = fmaf(pv1.w, cv1.w, a3);
    }
    if (i < n4) {
        float4 pv = __ldcs(p + i);
        float4 cv = __ldcs(c + i);
        a0 = fmaf(pv.x, cv.x, a0);
        a1 = fmaf(pv.y, cv.y, a1);
        a2 = fmaf(pv.z, cv.z, a2);
        a3 = fmaf(pv.w, cv.w, a3);
    }

    float s = (a0 + a1) + (a2 + a3);

    // warp reduce
    #pragma unroll
    for (int o = 16; o > 0; o >>= 1)
        s += __shfl_xor_sync(0xffffffffu, s, o);

    // block reduce across warps
    __shared__ float warp_sums[8];      // 256 threads = 8 warps
    int lane = threadIdx.x & 31;
    int wid  = threadIdx.x >> 5;
    if (lane == 0) warp_sums[wid] = s;
    __syncthreads();

    if (wid == 0) {
        float v = (lane < (blockDim.x >> 5)) ? warp_sums[lane] : 0.f;
        #pragma unroll
        for (int o = 4; o > 0; o >>= 1)
            v += __shfl_xor_sync(0xffffffffu, v, o);

        if (lane == 0) {
            atomicAdd(&g_acc, (double)v);
            __threadfence();
            unsigned int t = atomicInc(&g_count, gridDim.x - 1);
            if (t == gridDim.x - 1) {
                double total = atomicAdd(&g_acc, 0.0);  // coherent L2 read
                out[0] = (float)(total * inv_n);
                g_acc = 0.0;                            // reset for next replay
            }
        }
    }
}

extern "C" void kernel_launch(void* const* d_in, const int* in_sizes, int n_in,
                              void* d_out, int out_size) {
    const float4* probs     = (const float4*)d_in[0];
    const float4* centroids = (const float4*)d_in[1];
    float* out = (float*)d_out;

    long long total = (long long)in_sizes[0];     // 101,000,000 (divisible by 4)
    long long n4 = total >> 2;
    long long n_rows = (total % 101LL == 0) ? (total / 101LL) : 1000000LL;

    // Single persistent wave: 148 SMs x 5 resident CTAs (46 regs/thread -> 5).
    const int threads = 256;
    const int blocks  = 148 * 5;   // 740
    dot_kernel<<<blocks, threads>>>(probs, centroids, n4, out,
                                    1.0 / (double)n_rows);
}

// round 12
// speedup vs baseline: 1.0083x; 1.0041x over previous
#include <cuda_runtime.h>

// out = (1/N) * sum_i probs[i] * centroids[i], N*K = 101,000,000 fp32 elems.
// Pure HBM stream: 808 MB read once @ ~7.0 TB/s (88% DRAM-active).
// R9->R10: unroll-4 (8 x LDG.128 batched per iter) for denser DRAM request
// bursts, 32-bit index math (n4 < 2^31) to shrink the IMAD chains.

__device__ double g_acc;            // reset by last block each run (graph-replay safe)
__device__ unsigned int g_count;    // self-wraps via atomicInc(val = grid-1)

__global__ void __launch_bounds__(256)
dot_kernel(const float4* __restrict__ p,
           const float4* __restrict__ c,
           unsigned int n4,
           float* __restrict__ out,
           double inv_n) {
    float a0 = 0.f, a1 = 0.f, a2 = 0.f, a3 = 0.f;
    const unsigned int stride = gridDim.x * blockDim.x;        // 189,440
    unsigned int i = blockIdx.x * blockDim.x + threadIdx.x;

    // Unroll-4: 8 x LDG.128 (evict-first) issued back-to-back per iteration.
    for (; i + 3u * stride < n4; i += 4u * stride) {
        float4 pv0 = __ldcs(p + i);
        float4 cv0 = __ldcs(c + i);
        float4 pv1 = __ldcs(p + i + stride);
        float4 cv1 = __ldcs(c + i + stride);
        float4 pv2 = __ldcs(p + i + 2u * stride);
        float4 cv2 = __ldcs(c + i + 2u * stride);
        float4 pv3 = __ldcs(p + i + 3u * stride);
        float4 cv3 = __ldcs(c + i + 3u * stride);

        a0 = fmaf(pv0.x, cv0.x, a0);
        a1 = fmaf(pv0.y, cv0.y, a1);
        a2 = fmaf(pv0.z, cv0.z, a2);
        a3 = fmaf(pv0.w, cv0.w, a3);
        a0 = fmaf(pv1.x, cv1.x, a0);
        a1 = fmaf(pv1.y, cv1.y, a1);
        a2 = fmaf(pv1.z, cv1.z, a2);
        a3 = fmaf(pv1.w, cv1.w, a3);
        a0 = fmaf(pv2.x, cv2.x, a0);
        a1 = fmaf(pv2.y, cv2.y, a1);
        a2 = fmaf(pv2.z, cv2.z, a2);
        a3 = fmaf(pv2.w, cv2.w, a3);
        a0 = fmaf(pv3.x, cv3.x, a0);
        a1 = fmaf(pv3.y, cv3.y, a1);
        a2 = fmaf(pv3.z, cv3.z, a2);
        a3 = fmaf(pv3.w, cv3.w, a3);
    }
    // tail: at most 3 more strided elements per thread
    for (; i < n4; i += stride) {
        float4 pv = __ldcs(p + i);
        float4 cv = __ldcs(c + i);
        a0 = fmaf(pv.x, cv.x, a0);
        a1 = fmaf(pv.y, cv.y, a1);
        a2 = fmaf(pv.z, cv.z, a2);
        a3 = fmaf(pv.w, cv.w, a3);
    }

    float s = (a0 + a1) + (a2 + a3);

    // warp reduce
    #pragma unroll
    for (int o = 16; o > 0; o >>= 1)
        s += __shfl_xor_sync(0xffffffffu, s, o);

    // block reduce across warps
    __shared__ float warp_sums[8];      // 256 threads = 8 warps
    int lane = threadIdx.x & 31;
    int wid  = threadIdx.x >> 5;
    if (lane == 0) warp_sums[wid] = s;
    __syncthreads();

    if (wid == 0) {
        float v = (lane < (blockDim.x >> 5)) ? warp_sums[lane] : 0.f;
        #pragma unroll
        for (int o = 4; o > 0; o >>= 1)
            v += __shfl_xor_sync(0xffffffffu, v, o);

        if (lane == 0) {
            atomicAdd(&g_acc, (double)v);
            __threadfence();
            unsigned int t = atomicInc(&g_count, gridDim.x - 1);
            if (t == gridDim.x - 1) {
                double total = atomicAdd(&g_acc, 0.0);  // coherent L2 read
                out[0] = (float)(total * inv_n);
                g_acc = 0.0;                            // reset for next replay
            }
        }
    }
}

extern "C" void kernel_launch(void* const* d_in, const int* in_sizes, int n_in,
                              void* d_out, int out_size) {
    const float4* probs     = (const float4*)d_in[0];
    const float4* centroids = (const float4*)d_in[1];
    float* out = (float*)d_out;

    long long total = (long long)in_sizes[0];     // 101,000,000 (divisible by 4)
    unsigned int n4 = (unsigned int)(total >> 2); // 25,250,000 < 2^31
    long long n_rows = (total % 101LL == 0) ? (total / 101LL) : 1000000LL;

    // Single persistent wave: 148 SMs x 5 CTAs.
    const int threads = 256;
    const int blocks  = 148 * 5;   // 740
    dot_kernel<<<blocks, threads>>>(probs, centroids, n4, out,
                                    1.0 / (double)n_rows);
}